// round 5
// baseline (speedup 1.0000x reference)
#include <cuda_runtime.h>
#include <cuda_bf16.h>
#include <cstdint>

constexpr int BATCH = 2048;
constexpr int DIM   = 1024;
constexpr int MOL   = 8;
constexpr int NPAIR = 28;
constexpr int LQ    = 36;
constexpr int OUTD  = 4;
constexpr int MROWS = 32768;           // 2 * BATCH * MOL

__constant__ int c_pi[NPAIR] = {0,0,0,0,0,0,0,1,1,1,1,1,1,2,2,2,2,2,3,3,3,3,4,4,4,5,5,6};
__constant__ int c_pj[NPAIR] = {1,2,3,4,5,6,7,2,3,4,5,6,7,3,4,5,6,7,4,5,6,7,5,6,7,6,7,7};

// ------------------------- static device scratch ---------------------------
__device__ __nv_bfloat16 g_WqHi[DIM * DIM];
__device__ __nv_bfloat16 g_WqLo[DIM * DIM];
__device__ __nv_bfloat16 g_WkHi[DIM * DIM];
__device__ __nv_bfloat16 g_WkLo[DIM * DIM];
__device__ __nv_bfloat16 g_GtHi[DIM * DIM];          // Gt[n][k] = G[k][n]
__device__ __nv_bfloat16 g_GtLo[DIM * DIM];
__device__ __nv_bfloat16 g_Xhi[(size_t)MROWS * DIM]; // 64 MB, row = s*16384+b*8+m
__device__ __nv_bfloat16 g_Xlo[(size_t)MROWS * DIM]; // 64 MB
__device__ float         g_G[DIM * DIM];             // fp32 Wq @ Wk^T
__device__ float         g_Spart[8ull * 2 * BATCH * 64];  // 4 MB partial grams
__device__ float         g_w[2 * BATCH * MOL];

// ------------------------------ helpers ------------------------------------
__device__ __forceinline__ uint32_t s2u(const void* p) {
    uint32_t a;
    asm("{ .reg .u64 t; cvta.to.shared.u64 t, %1; cvt.u32.u64 %0, t; }" : "=r"(a) : "l"(p));
    return a;
}
__device__ __forceinline__ void cpa16(uint32_t d, const void* g) {
    asm volatile("cp.async.cg.shared.global [%0], [%1], 16;" :: "r"(d), "l"(g));
}
#define CP_COMMIT()  asm volatile("cp.async.commit_group;" ::: "memory")
#define CP_WAIT1()   asm volatile("cp.async.wait_group 1;" ::: "memory")
#define CP_WAIT0()   asm volatile("cp.async.wait_group 0;" ::: "memory")

__device__ __forceinline__ float4 lds4f(uint32_t a) {
    float4 v;
    asm volatile("ld.shared.v4.f32 {%0,%1,%2,%3}, [%4];"
        : "=f"(v.x), "=f"(v.y), "=f"(v.z), "=f"(v.w) : "r"(a));
    return v;
}
__device__ __forceinline__ void sts2f(uint32_t a, float x, float y) {
    asm volatile("st.shared.v2.f32 [%0], {%1,%2};" :: "r"(a), "f"(x), "f"(y));
}

__device__ __forceinline__ void lda4(uint32_t* f, uint32_t mbase, int wm, int mt,
                                     int ks, int lane) {
    int g = lane >> 3, r = lane & 7;
    int mloc = wm + mt * 16 + (g & 1) * 8 + r;
    int kloc = ks * 16 + (g >> 1) * 8;
    uint32_t a = mbase + (mloc * 40 + kloc) * 2;
    asm volatile("ldmatrix.sync.aligned.m8n8.x4.shared.b16 {%0,%1,%2,%3}, [%4];"
        : "=r"(f[0]), "=r"(f[1]), "=r"(f[2]), "=r"(f[3]) : "r"(a));
}
__device__ __forceinline__ void ldb2(uint32_t* f, uint32_t mbase, int wn, int nt,
                                     int ks, int lane) {
    int l = lane & 15;
    int g = l >> 3, r = l & 7;
    int nloc = wn + nt * 8 + r;
    int kloc = ks * 16 + g * 8;
    uint32_t a = mbase + (nloc * 40 + kloc) * 2;
    asm volatile("ldmatrix.sync.aligned.m8n8.x2.shared.b16 {%0,%1}, [%2];"
        : "=r"(f[0]), "=r"(f[1]) : "r"(a));
}
__device__ __forceinline__ void mma16816(float* c, const uint32_t* a, const uint32_t* b) {
    asm volatile("mma.sync.aligned.m16n8k16.row.col.f32.bf16.bf16.f32 "
        "{%0,%1,%2,%3}, {%4,%5,%6,%7}, {%8,%9}, {%0,%1,%2,%3};"
        : "+f"(c[0]), "+f"(c[1]), "+f"(c[2]), "+f"(c[3])
        : "r"(a[0]), "r"(a[1]), "r"(a[2]), "r"(a[3]), "r"(b[0]), "r"(b[1]));
}

union BfPack { __nv_bfloat16 h[8]; uint4 u; };

// ------------------------- split kernels -----------------------------------
// one row per block (128 thr x 8 elems); grid 2048 = {Wq rows, Wk rows}
__global__ void __launch_bounds__(128) split_w(const float* __restrict__ Wq,
                                               const float* __restrict__ Wk) {
    int bx = blockIdx.x;
    int mat = bx >> 10, row = bx & 1023;
    const float* src = (mat ? Wk : Wq) + (size_t)row * DIM;
    __nv_bfloat16* hi = (mat ? g_WkHi : g_WqHi) + (size_t)row * DIM;
    __nv_bfloat16* lo = (mat ? g_WkLo : g_WqLo) + (size_t)row * DIM;
    int t = threadIdx.x;
    float4 v0 = ((const float4*)src)[t * 2];
    float4 v1 = ((const float4*)src)[t * 2 + 1];
    float vv[8] = {v0.x, v0.y, v0.z, v0.w, v1.x, v1.y, v1.z, v1.w};
    BfPack hp, lp;
#pragma unroll
    for (int i = 0; i < 8; i++) {
        __nv_bfloat16 h = __float2bfloat16_rn(vv[i]);
        hp.h[i] = h;
        lp.h[i] = __float2bfloat16_rn(vv[i] - __bfloat162float(h));
    }
    ((uint4*)(hi))[t] = hp.u;
    ((uint4*)(lo))[t] = lp.u;
}

// X split-gather: row = s*16384 + b*8 + m -> feats[m, b, :]; 2 rows per block
__global__ void __launch_bounds__(256) split_x(const float* __restrict__ p,
                                               const float* __restrict__ r) {
    int t = threadIdx.x;
    int row = blockIdx.x * 2 + (t >> 7);
    int tt = t & 127;
    int s = row >> 14, b = (row >> 3) & (BATCH - 1), m = row & 7;
    const float* src = (s ? r : p) + ((size_t)m * BATCH + b) * DIM;
    float4 v0 = ((const float4*)src)[tt * 2];
    float4 v1 = ((const float4*)src)[tt * 2 + 1];
    float vv[8] = {v0.x, v0.y, v0.z, v0.w, v1.x, v1.y, v1.z, v1.w};
    BfPack hp, lp;
#pragma unroll
    for (int i = 0; i < 8; i++) {
        __nv_bfloat16 h = __float2bfloat16_rn(vv[i]);
        hp.h[i] = h;
        lp.h[i] = __float2bfloat16_rn(vv[i] - __bfloat162float(h));
    }
    ((uint4*)(g_Xhi + (size_t)row * DIM))[tt] = hp.u;
    ((uint4*)(g_Xlo + (size_t)row * DIM))[tt] = lp.u;
}

// transpose fp32 G -> bf16 hi/lo Gt (Gt[n][k] = G[k][n])
__global__ void tsplit_g() {
    __shared__ float tile[32][33];
    int tx = threadIdx.x, ty = threadIdx.y;
    int x = blockIdx.x * 32 + tx;
    int y0 = blockIdx.y * 32;
#pragma unroll
    for (int i = ty; i < 32; i += 8)
        tile[i][tx] = g_G[(size_t)(y0 + i) * DIM + x];
    __syncthreads();
    int k2 = y0 + tx;
#pragma unroll
    for (int i = ty; i < 32; i += 8) {
        float v = tile[tx][i];
        __nv_bfloat16 h = __float2bfloat16_rn(v);
        size_t o = (size_t)(blockIdx.x * 32 + i) * DIM + k2;
        g_GtHi[o] = h;
        g_GtLo[o] = __float2bfloat16_rn(v - __bfloat162float(h));
    }
}

// ------------------------- mma.sync split GEMM -----------------------------
// C = Ahi*Bhi + Alo*Bhi + Ahi*Blo  (A row-major [M,K]; B K-major [N,K])
// CTA 128x128, K-chunk 32, 2-stage cp.async, 8 warps of 64x32.
// fuse=0: store fp32 C.   fuse=1: gram epilogue -> g_Spart, no C store.
constexpr int MAT_ELE   = 128 * 40;
constexpr int STAGE_B   = 4 * MAT_ELE * 2;      // 40960 bytes
constexpr int SMEM_GEMM = 2 * STAGE_B;          // 81920 bytes
constexpr int FPAD      = 132;                  // fp32 smem row stride (words)

__device__ __forceinline__ void load_chunk(
    uint32_t sbase, int stage,
    const __nv_bfloat16* __restrict__ Ahi, const __nv_bfloat16* __restrict__ Alo,
    const __nv_bfloat16* __restrict__ Bhi, const __nv_bfloat16* __restrict__ Blo,
    int rowBase, int colBase, int k0, int tid)
{
    uint32_t st = sbase + stage * STAGE_B;
#pragma unroll
    for (int mat = 0; mat < 4; mat++) {
        const __nv_bfloat16* src0 =
            (mat == 0) ? Ahi : (mat == 1) ? Alo : (mat == 2) ? Bhi : Blo;
        int base = (mat < 2) ? rowBase : colBase;
#pragma unroll
        for (int h = 0; h < 2; h++) {
            int idx = h * 256 + tid;
            int row = idx >> 2, ch = idx & 3;
            const __nv_bfloat16* src = src0 + (size_t)(base + row) * DIM + k0 + ch * 8;
            uint32_t dst = st + (mat * MAT_ELE + row * 40 + ch * 8) * 2;
            cpa16(dst, src);
        }
    }
    CP_COMMIT();
}

__global__ void __launch_bounds__(256) mma_gemm(
    const __nv_bfloat16* __restrict__ Ahi, const __nv_bfloat16* __restrict__ Alo,
    const __nv_bfloat16* __restrict__ Bhi, const __nv_bfloat16* __restrict__ Blo,
    float* __restrict__ C, int fuse,
    const float* __restrict__ fR, const float* __restrict__ fP)
{
    extern __shared__ char smem[];
    uint32_t sbase = s2u(smem);
    const int tid  = threadIdx.x;
    const int lane = tid & 31;
    const int wid  = tid >> 5;
    const int wm = (wid >> 2) * 64;
    const int wn = (wid & 3) * 32;
    const int rowBase = blockIdx.x * 128;
    const int colBase = blockIdx.y * 128;

    float acc[4][4][4];
#pragma unroll
    for (int i = 0; i < 4; i++)
#pragma unroll
        for (int j = 0; j < 4; j++)
#pragma unroll
            for (int q = 0; q < 4; q++) acc[i][j][q] = 0.f;

    load_chunk(sbase, 0, Ahi, Alo, Bhi, Blo, rowBase, colBase, 0, tid);

    for (int c = 0; c < 32; ++c) {
        int s = c & 1;
        if (c < 31) {
            load_chunk(sbase, s ^ 1, Ahi, Alo, Bhi, Blo, rowBase, colBase,
                       (c + 1) * 32, tid);
            CP_WAIT1();
        } else {
            CP_WAIT0();
        }
        __syncthreads();

        uint32_t stb = sbase + s * STAGE_B;
        uint32_t bAhi = stb;
        uint32_t bAlo = stb + MAT_ELE * 2;
        uint32_t bBhi = stb + 2 * MAT_ELE * 2;
        uint32_t bBlo = stb + 3 * MAT_ELE * 2;

#pragma unroll
        for (int ks = 0; ks < 2; ks++) {
            uint32_t ahif[4][4], alof[4][4], bhif[4][2], blof[4][2];
#pragma unroll
            for (int mt = 0; mt < 4; mt++) {
                lda4(ahif[mt], bAhi, wm, mt, ks, lane);
                lda4(alof[mt], bAlo, wm, mt, ks, lane);
            }
#pragma unroll
            for (int nt = 0; nt < 4; nt++) {
                ldb2(bhif[nt], bBhi, wn, nt, ks, lane);
                ldb2(blof[nt], bBlo, wn, nt, ks, lane);
            }
#pragma unroll
            for (int mt = 0; mt < 4; mt++)
#pragma unroll
                for (int nt = 0; nt < 4; nt++) {
                    mma16816(acc[mt][nt], ahif[mt], bhif[nt]);
                    mma16816(acc[mt][nt], alof[mt], bhif[nt]);
                    mma16816(acc[mt][nt], ahif[mt], blof[nt]);
                }
        }
        __syncthreads();
    }

    if (!fuse) {
#pragma unroll
        for (int mt = 0; mt < 4; mt++) {
            int r0 = rowBase + wm + mt * 16 + (lane >> 2);
#pragma unroll
            for (int nt = 0; nt < 4; nt++) {
                int col = colBase + wn + nt * 8 + (lane & 3) * 2;
                *(float2*)&C[(size_t)r0 * DIM + col] =
                    make_float2(acc[mt][nt][0], acc[mt][nt][1]);
                *(float2*)&C[(size_t)(r0 + 8) * DIM + col] =
                    make_float2(acc[mt][nt][2], acc[mt][nt][3]);
            }
        }
        return;
    }

    // ---------------- fused gram epilogue ----------------
    // tile rows: side = rowBase>>14, batches bb..bb+15, all 8 query mols
    const int side = blockIdx.x >> 7;
    const int bb = (blockIdx.x & 127) * 16;
    const float* keys = side ? fP : fR;      // side0 keys=r, side1 keys=p
    uint32_t zsm = sbase;                    // 64 x FPAD fp32 (Z half-tile)
    uint32_t fsm = sbase + 64 * FPAD * 4;    // 64 x FPAD fp32 (F half-tile)

#pragma unroll
    for (int pass = 0; pass < 2; pass++) {
        __syncthreads();   // prev-pass gram reads / mainloop smem reads done
        if ((wid >> 2) == pass) {            // this warp group's acc is the Z half
#pragma unroll
            for (int mt = 0; mt < 4; mt++) {
                int lr = mt * 16 + (lane >> 2);
#pragma unroll
                for (int nt = 0; nt < 4; nt++) {
                    int lc = wn + nt * 8 + (lane & 3) * 2;
                    sts2f(zsm + (lr * FPAD + lc) * 4, acc[mt][nt][0], acc[mt][nt][1]);
                    sts2f(zsm + ((lr + 8) * FPAD + lc) * 4, acc[mt][nt][2], acc[mt][nt][3]);
                }
            }
        }
        // all threads: cp.async the key-feat half-tile (8 batches x 8 mols x 128 d)
#pragma unroll
        for (int h = 0; h < 8; h++) {
            int idx = h * 256 + tid;          // 0..2047 = 64 rows x 32 16B-chunks
            int rowi = idx >> 5, ch = idx & 31;
            int bl = rowi >> 3, kk2 = rowi & 7;
            const float* src = keys +
                ((size_t)kk2 * BATCH + (bb + pass * 8 + bl)) * DIM + colBase + ch * 4;
            cpa16(fsm + (rowi * FPAD + ch * 4) * 4, src);
        }
        CP_COMMIT(); CP_WAIT0();
        __syncthreads();

        // warp = local batch; lane -> (q,k) pairs; dot length 128
        int bl = wid, kk = lane & 7;
#pragma unroll
        for (int i = 0; i < 2; i++) {
            int q = (lane >> 3) + i * 4;
            uint32_t zr = zsm + ((bl * 8 + q) * FPAD) * 4;
            uint32_t fr = fsm + ((bl * 8 + kk) * FPAD) * 4;
            float s = 0.f;
#pragma unroll
            for (int cc = 0; cc < 128; cc += 4) {
                float4 zv = lds4f(zr + cc * 4);
                float4 fv = lds4f(fr + cc * 4);
                s += zv.x * fv.x + zv.y * fv.y + zv.z * fv.z + zv.w * fv.w;
            }
            g_Spart[((size_t)(blockIdx.y * 2 + side) * BATCH + bb + pass * 8 + bl) * 64
                    + lane + 32 * i] = s;
        }
    }
}

// -------------------- softmax / attention outputs --------------------------
__global__ void __launch_bounds__(128) softmax_kernel(float* __restrict__ d_out) {
    const int b = blockIdx.x;
    const int t = threadIdx.x;
    __shared__ float sS[2][MOL][MOL];
    __shared__ float sProb[2][LQ][LQ];
    __shared__ float sAtt[2][LQ];

    {
        int side = t >> 6, e = t & 63;
        float s = 0.f;
#pragma unroll
        for (int ct = 0; ct < 8; ct++)
            s += g_Spart[((size_t)(ct * 2 + side) * BATCH + b) * 64 + e];
        sS[side][e >> 3][e & 7] = s;
    }
    __syncthreads();

    if (t < 2 * LQ) {
        int sd = t / LQ, qq = t % LQ;
        int qi, qj;
        if (qq < MOL) { qi = qq; qj = -1; }
        else          { qi = c_pi[qq - MOL]; qj = c_pj[qq - MOL]; }
        float row[LQ];
        float maxv = -1e30f;
#pragma unroll
        for (int kk = 0; kk < LQ; kk++) {
            int ki, kj;
            if (kk < MOL) { ki = kk; kj = -1; }
            else          { ki = c_pi[kk - MOL]; kj = c_pj[kk - MOL]; }
            float v = sS[sd][qi][ki];
            if (kj >= 0) v += sS[sd][qi][kj];
            if (qj >= 0) {
                v += sS[sd][qj][ki];
                if (kj >= 0) v += sS[sd][qj][kj];
            }
            v *= 0.03125f;
            row[kk] = v;
            maxv = fmaxf(maxv, v);
        }
        float sum = 0.f;
#pragma unroll
        for (int kk = 0; kk < LQ; kk++) { row[kk] = expf(row[kk] - maxv); sum += row[kk]; }
        float inv = 1.f / sum;
#pragma unroll
        for (int kk = 0; kk < LQ; kk++) sProb[sd][qq][kk] = row[kk] * inv;
    }
    __syncthreads();

    if (t < 2 * LQ) {
        int sd = t / LQ, kk = t % LQ;
        float a = 0.f;
#pragma unroll
        for (int qq = 0; qq < LQ; qq++) a += sProb[sd][qq][kk];
        a *= (1.0f / LQ);
        sAtt[sd][kk] = a;
        d_out[BATCH * OUTD + sd * (BATCH * LQ) + b * LQ + kk] = a;
    }
    __syncthreads();

    if (t < 16) {
        int sd = t >> 3, m = t & 7;
        float w = sAtt[sd][m];
#pragma unroll
        for (int pp = 0; pp < NPAIR; pp++)
            if (c_pi[pp] == m || c_pj[pp] == m) w += sAtt[sd][MOL + pp];
        g_w[sd * BATCH * MOL + b * MOL + m] = w;
    }
}

// ------------------------- pooling + head (float4) -------------------------
__global__ void __launch_bounds__(256) pool_kernel(
    const float* __restrict__ r_feats, const float* __restrict__ p_feats,
    const float* __restrict__ r_new,   const float* __restrict__ p_new,
    const float* __restrict__ W_pred,  const float* __restrict__ b_pred,
    float* __restrict__ d_out)
{
    const int b = blockIdx.x;
    const int t = threadIdx.x;
    __shared__ float sw[16];
    __shared__ float sRed[OUTD][8];
    if (t < 16) sw[t] = g_w[(t >> 3) * BATCH * MOL + b * MOL + (t & 7)];
    __syncthreads();

    const int d = t * 4;
    float4 acc = make_float4(0.f, 0.f, 0.f, 0.f);
#pragma unroll
    for (int m = 0; m < MOL; m++) {
        size_t off = ((size_t)m * BATCH + b) * DIM + d;
        float4 a  = *(const float4*)(r_feats + off);
        float4 an = *(const float4*)(r_new + off);
        float4 pv = *(const float4*)(p_feats + off);
        float4 pn = *(const float4*)(p_new + off);
        float wr = sw[m], wp = sw[8 + m];
        acc.x += wr * (a.x + an.x) - wp * (pv.x + pn.x);
        acc.y += wr * (a.y + an.y) - wp * (pv.y + pn.y);
        acc.z += wr * (a.z + an.z) - wp * (pv.z + pn.z);
        acc.w += wr * (a.w + an.w) - wp * (pv.w + pn.w);
    }
    float part[OUTD];
#pragma unroll
    for (int o = 0; o < OUTD; o++) {
        float4 wv = *(const float4*)(W_pred + (size_t)o * DIM + d);
        part[o] = acc.x * wv.x + acc.y * wv.y + acc.z * wv.z + acc.w * wv.w;
    }
    int lane = t & 31, wid = t >> 5;
#pragma unroll
    for (int o = 0; o < OUTD; o++) {
        float v = part[o];
#pragma unroll
        for (int off = 16; off > 0; off >>= 1)
            v += __shfl_down_sync(0xFFFFFFFFu, v, off);
        if (lane == 0) sRed[o][wid] = v;
    }
    __syncthreads();
    if (t < OUTD) {
        float s = 0.f;
#pragma unroll
        for (int w = 0; w < 8; w++) s += sRed[t][w];
        d_out[b * OUTD + t] = s + b_pred[t];
    }
}

// ---------------------------------------------------------------------------
extern "C" void kernel_launch(void* const* d_in, const int* in_sizes, int n_in,
                              void* d_out, int out_size) {
    const float* r_feats = (const float*)d_in[0];
    const float* p_feats = (const float*)d_in[1];
    const float* r_new   = (const float*)d_in[2];
    const float* p_new   = (const float*)d_in[3];
    const float* Wq      = (const float*)d_in[4];
    const float* Wk      = (const float*)d_in[5];
    const float* W_pred  = (const float*)d_in[6];
    const float* b_pred  = (const float*)d_in[7];
    float* out = (float*)d_out;

    cudaFuncSetAttribute(mma_gemm, cudaFuncAttributeMaxDynamicSharedMemorySize,
                         SMEM_GEMM);

    __nv_bfloat16 *WqHi, *WqLo, *WkHi, *WkLo, *GtHi, *GtLo, *Xhi, *Xlo;
    float *G;
    cudaGetSymbolAddress((void**)&WqHi, g_WqHi);
    cudaGetSymbolAddress((void**)&WqLo, g_WqLo);
    cudaGetSymbolAddress((void**)&WkHi, g_WkHi);
    cudaGetSymbolAddress((void**)&WkLo, g_WkLo);
    cudaGetSymbolAddress((void**)&GtHi, g_GtHi);
    cudaGetSymbolAddress((void**)&GtLo, g_GtLo);
    cudaGetSymbolAddress((void**)&Xhi,  g_Xhi);
    cudaGetSymbolAddress((void**)&Xlo,  g_Xlo);
    cudaGetSymbolAddress((void**)&G,    g_G);

    // 1) weight splits
    split_w<<<2048, 128>>>(Wq, Wk);
    // 2) G = Wq @ Wk^T (Wk rows are already [N,K] K-major)
    mma_gemm<<<dim3(8, 8), 256, SMEM_GEMM>>>(WqHi, WqLo, WkHi, WkLo, G, 0,
                                             nullptr, nullptr);
    // 3) transpose+split G -> Gt
    tsplit_g<<<dim3(32, 32), dim3(32, 8)>>>();
    // 4) gather+split X (packed 128-bit stores)
    split_x<<<MROWS / 2, 256>>>(p_feats, r_feats);
    // 5) Z = X @ G with fused gram epilogue -> g_Spart (Z never materialized)
    mma_gemm<<<dim3(256, 8), 256, SMEM_GEMM>>>(Xhi, Xlo, GtHi, GtLo, nullptr, 1,
                                               r_feats, p_feats);
    // 6) reduce partials -> softmax -> att outputs + pooling weights
    softmax_kernel<<<BATCH, 128>>>(out);
    // 7) pooling + head
    pool_kernel<<<BATCH, 256>>>(r_feats, p_feats, r_new, p_new, W_pred, b_pred, out);
}

// round 6
// speedup vs baseline: 1.1834x; 1.1834x over previous
#include <cuda_runtime.h>
#include <cuda_bf16.h>
#include <cstdint>

constexpr int BATCH = 2048;
constexpr int DIM   = 1024;
constexpr int MOL   = 8;
constexpr int NPAIR = 28;
constexpr int LQ    = 36;
constexpr int OUTD  = 4;
constexpr int MROWS = 32768;           // 2 * BATCH * MOL

__constant__ int c_pi[NPAIR] = {0,0,0,0,0,0,0,1,1,1,1,1,1,2,2,2,2,2,3,3,3,3,4,4,4,5,5,6};
__constant__ int c_pj[NPAIR] = {1,2,3,4,5,6,7,2,3,4,5,6,7,3,4,5,6,7,4,5,6,7,5,6,7,6,7,7};

// ------------------------- static device scratch ---------------------------
__device__ __nv_bfloat16 g_WqHi[DIM * DIM];
__device__ __nv_bfloat16 g_WqLo[DIM * DIM];
__device__ __nv_bfloat16 g_WkHi[DIM * DIM];
__device__ __nv_bfloat16 g_WkLo[DIM * DIM];
__device__ __nv_bfloat16 g_GtHi[DIM * DIM];          // Gt[n][k] = G[k][n]
__device__ __nv_bfloat16 g_GtLo[DIM * DIM];
__device__ __nv_bfloat16 g_Xhi[(size_t)MROWS * DIM]; // 64 MB, row = s*16384+b*8+m
__device__ __nv_bfloat16 g_Xlo[(size_t)MROWS * DIM]; // 64 MB
__device__ float         g_G[DIM * DIM];             // fp32 Wq @ Wk^T
__device__ float         g_Spart[8ull * 2 * BATCH * 64];  // 4 MB partial grams
__device__ float         g_w[2 * BATCH * MOL];

// ------------------------------ helpers ------------------------------------
__device__ __forceinline__ uint32_t s2u(const void* p) {
    uint32_t a;
    asm("{ .reg .u64 t; cvta.to.shared.u64 t, %1; cvt.u32.u64 %0, t; }" : "=r"(a) : "l"(p));
    return a;
}
__device__ __forceinline__ void cpa16(uint32_t d, const void* g) {
    asm volatile("cp.async.cg.shared.global [%0], [%1], 16;" :: "r"(d), "l"(g));
}
#define CP_COMMIT()  asm volatile("cp.async.commit_group;" ::: "memory")
#define CP_WAIT1()   asm volatile("cp.async.wait_group 1;" ::: "memory")
#define CP_WAIT0()   asm volatile("cp.async.wait_group 0;" ::: "memory")

__device__ __forceinline__ float4 lds4f(uint32_t a) {
    float4 v;
    asm volatile("ld.shared.v4.f32 {%0,%1,%2,%3}, [%4];"
        : "=f"(v.x), "=f"(v.y), "=f"(v.z), "=f"(v.w) : "r"(a));
    return v;
}
__device__ __forceinline__ void sts2f(uint32_t a, float x, float y) {
    asm volatile("st.shared.v2.f32 [%0], {%1,%2};" :: "r"(a), "f"(x), "f"(y));
}

__device__ __forceinline__ void lda4(uint32_t* f, uint32_t mbase, int wm, int mt,
                                     int ks, int lane) {
    int g = lane >> 3, r = lane & 7;
    int mloc = wm + mt * 16 + (g & 1) * 8 + r;
    int kloc = ks * 16 + (g >> 1) * 8;
    uint32_t a = mbase + (mloc * 40 + kloc) * 2;
    asm volatile("ldmatrix.sync.aligned.m8n8.x4.shared.b16 {%0,%1,%2,%3}, [%4];"
        : "=r"(f[0]), "=r"(f[1]), "=r"(f[2]), "=r"(f[3]) : "r"(a));
}
__device__ __forceinline__ void ldb2(uint32_t* f, uint32_t mbase, int wn, int nt,
                                     int ks, int lane) {
    int l = lane & 15;
    int g = l >> 3, r = l & 7;
    int nloc = wn + nt * 8 + r;
    int kloc = ks * 16 + g * 8;
    uint32_t a = mbase + (nloc * 40 + kloc) * 2;
    asm volatile("ldmatrix.sync.aligned.m8n8.x2.shared.b16 {%0,%1}, [%2];"
        : "=r"(f[0]), "=r"(f[1]) : "r"(a));
}
__device__ __forceinline__ void mma16816(float* c, const uint32_t* a, const uint32_t* b) {
    asm volatile("mma.sync.aligned.m16n8k16.row.col.f32.bf16.bf16.f32 "
        "{%0,%1,%2,%3}, {%4,%5,%6,%7}, {%8,%9}, {%0,%1,%2,%3};"
        : "+f"(c[0]), "+f"(c[1]), "+f"(c[2]), "+f"(c[3])
        : "r"(a[0]), "r"(a[1]), "r"(a[2]), "r"(a[3]), "r"(b[0]), "r"(b[1]));
}

union BfPack { __nv_bfloat16 h[8]; uint4 u; };

// ------------------------- split kernels -----------------------------------
__global__ void __launch_bounds__(128) split_w(const float* __restrict__ Wq,
                                               const float* __restrict__ Wk) {
    int bx = blockIdx.x;
    int mat = bx >> 10, row = bx & 1023;
    const float* src = (mat ? Wk : Wq) + (size_t)row * DIM;
    __nv_bfloat16* hi = (mat ? g_WkHi : g_WqHi) + (size_t)row * DIM;
    __nv_bfloat16* lo = (mat ? g_WkLo : g_WqLo) + (size_t)row * DIM;
    int t = threadIdx.x;
    float4 v0 = ((const float4*)src)[t * 2];
    float4 v1 = ((const float4*)src)[t * 2 + 1];
    float vv[8] = {v0.x, v0.y, v0.z, v0.w, v1.x, v1.y, v1.z, v1.w};
    BfPack hp, lp;
#pragma unroll
    for (int i = 0; i < 8; i++) {
        __nv_bfloat16 h = __float2bfloat16_rn(vv[i]);
        hp.h[i] = h;
        lp.h[i] = __float2bfloat16_rn(vv[i] - __bfloat162float(h));
    }
    ((uint4*)(hi))[t] = hp.u;
    ((uint4*)(lo))[t] = lp.u;
}

__global__ void __launch_bounds__(256) split_x(const float* __restrict__ p,
                                               const float* __restrict__ r) {
    int t = threadIdx.x;
    int row = blockIdx.x * 2 + (t >> 7);
    int tt = t & 127;
    int s = row >> 14, b = (row >> 3) & (BATCH - 1), m = row & 7;
    const float* src = (s ? r : p) + ((size_t)m * BATCH + b) * DIM;
    float4 v0 = ((const float4*)src)[tt * 2];
    float4 v1 = ((const float4*)src)[tt * 2 + 1];
    float vv[8] = {v0.x, v0.y, v0.z, v0.w, v1.x, v1.y, v1.z, v1.w};
    BfPack hp, lp;
#pragma unroll
    for (int i = 0; i < 8; i++) {
        __nv_bfloat16 h = __float2bfloat16_rn(vv[i]);
        hp.h[i] = h;
        lp.h[i] = __float2bfloat16_rn(vv[i] - __bfloat162float(h));
    }
    ((uint4*)(g_Xhi + (size_t)row * DIM))[tt] = hp.u;
    ((uint4*)(g_Xlo + (size_t)row * DIM))[tt] = lp.u;
}

__global__ void tsplit_g() {
    __shared__ float tile[32][33];
    int tx = threadIdx.x, ty = threadIdx.y;
    int x = blockIdx.x * 32 + tx;
    int y0 = blockIdx.y * 32;
#pragma unroll
    for (int i = ty; i < 32; i += 8)
        tile[i][tx] = g_G[(size_t)(y0 + i) * DIM + x];
    __syncthreads();
    int k2 = y0 + tx;
#pragma unroll
    for (int i = ty; i < 32; i += 8) {
        float v = tile[tx][i];
        __nv_bfloat16 h = __float2bfloat16_rn(v);
        size_t o = (size_t)(blockIdx.x * 32 + i) * DIM + k2;
        g_GtHi[o] = h;
        g_GtLo[o] = __float2bfloat16_rn(v - __bfloat162float(h));
    }
}

// ------------------------- shared GEMM machinery ---------------------------
constexpr int MAT_ELE   = 128 * 40;
constexpr int STAGE_B   = 4 * MAT_ELE * 2;      // 40960 bytes
constexpr int SMEM_GEMM = 2 * STAGE_B;          // 81920 bytes
constexpr int FPAD      = 132;

__device__ __forceinline__ void load_chunk(
    uint32_t sbase, int stage,
    const __nv_bfloat16* __restrict__ Ahi, const __nv_bfloat16* __restrict__ Alo,
    const __nv_bfloat16* __restrict__ Bhi, const __nv_bfloat16* __restrict__ Blo,
    int rowBase, int colBase, int k0, int tid)
{
    uint32_t st = sbase + stage * STAGE_B;
#pragma unroll
    for (int mat = 0; mat < 4; mat++) {
        const __nv_bfloat16* src0 =
            (mat == 0) ? Ahi : (mat == 1) ? Alo : (mat == 2) ? Bhi : Blo;
        int base = (mat < 2) ? rowBase : colBase;
#pragma unroll
        for (int h = 0; h < 2; h++) {
            int idx = h * 256 + tid;
            int row = idx >> 2, ch = idx & 3;
            const __nv_bfloat16* src = src0 + (size_t)(base + row) * DIM + k0 + ch * 8;
            uint32_t dst = st + (mat * MAT_ELE + row * 40 + ch * 8) * 2;
            cpa16(dst, src);
        }
    }
    CP_COMMIT();
}

// inner compute for one k32 chunk in stage s; B frags held, A streamed per mt
__device__ __forceinline__ void compute_chunk(
    float acc[4][4][4], uint32_t stb, int wm, int wn, int lane)
{
    uint32_t bAhi = stb;
    uint32_t bAlo = stb + MAT_ELE * 2;
    uint32_t bBhi = stb + 2 * MAT_ELE * 2;
    uint32_t bBlo = stb + 3 * MAT_ELE * 2;
#pragma unroll
    for (int ks = 0; ks < 2; ks++) {
        uint32_t bhif[4][2], blof[4][2];
#pragma unroll
        for (int nt = 0; nt < 4; nt++) {
            ldb2(bhif[nt], bBhi, wn, nt, ks, lane);
            ldb2(blof[nt], bBlo, wn, nt, ks, lane);
        }
#pragma unroll
        for (int mt = 0; mt < 4; mt++) {
            uint32_t ahif[4], alof[4];
            lda4(ahif, bAhi, wm, mt, ks, lane);
            lda4(alof, bAlo, wm, mt, ks, lane);
#pragma unroll
            for (int nt = 0; nt < 4; nt++) {
                mma16816(acc[mt][nt], ahif, bhif[nt]);
                mma16816(acc[mt][nt], alof, bhif[nt]);
                mma16816(acc[mt][nt], ahif, blof[nt]);
            }
        }
    }
}

// ------------------- plain GEMM (G = Wq@Wk^T), stores C --------------------
__global__ void __launch_bounds__(256) mma_gemm_plain(
    const __nv_bfloat16* __restrict__ Ahi, const __nv_bfloat16* __restrict__ Alo,
    const __nv_bfloat16* __restrict__ Bhi, const __nv_bfloat16* __restrict__ Blo,
    float* __restrict__ C)
{
    extern __shared__ char smem[];
    uint32_t sbase = s2u(smem);
    const int tid  = threadIdx.x;
    const int lane = tid & 31;
    const int wid  = tid >> 5;
    const int wm = (wid >> 2) * 64;
    const int wn = (wid & 3) * 32;
    const int rowBase = blockIdx.x * 128;
    const int colBase = blockIdx.y * 128;

    float acc[4][4][4];
#pragma unroll
    for (int i = 0; i < 4; i++)
#pragma unroll
        for (int j = 0; j < 4; j++)
#pragma unroll
            for (int q = 0; q < 4; q++) acc[i][j][q] = 0.f;

    load_chunk(sbase, 0, Ahi, Alo, Bhi, Blo, rowBase, colBase, 0, tid);
    for (int c = 0; c < 32; ++c) {
        int s = c & 1;
        if (c < 31) {
            load_chunk(sbase, s ^ 1, Ahi, Alo, Bhi, Blo, rowBase, colBase,
                       (c + 1) * 32, tid);
            CP_WAIT1();
        } else {
            CP_WAIT0();
        }
        __syncthreads();
        compute_chunk(acc, sbase + s * STAGE_B, wm, wn, lane);
        __syncthreads();
    }

#pragma unroll
    for (int mt = 0; mt < 4; mt++) {
        int r0 = rowBase + wm + mt * 16 + (lane >> 2);
#pragma unroll
        for (int nt = 0; nt < 4; nt++) {
            int col = colBase + wn + nt * 8 + (lane & 3) * 2;
            *(float2*)&C[(size_t)r0 * DIM + col] =
                make_float2(acc[mt][nt][0], acc[mt][nt][1]);
            *(float2*)&C[(size_t)(r0 + 8) * DIM + col] =
                make_float2(acc[mt][nt][2], acc[mt][nt][3]);
        }
    }
}

// --------------- fused GEMM (Z = X@G) + gram epilogue ----------------------
__global__ void __launch_bounds__(256, 2) mma_gemm_fused(
    const __nv_bfloat16* __restrict__ Ahi, const __nv_bfloat16* __restrict__ Alo,
    const __nv_bfloat16* __restrict__ Bhi, const __nv_bfloat16* __restrict__ Blo,
    const float* __restrict__ fR, const float* __restrict__ fP)
{
    extern __shared__ char smem[];
    uint32_t sbase = s2u(smem);
    const int tid  = threadIdx.x;
    const int lane = tid & 31;
    const int wid  = tid >> 5;
    const int wm = (wid >> 2) * 64;
    const int wn = (wid & 3) * 32;
    const int rowBase = blockIdx.x * 128;
    const int colBase = blockIdx.y * 128;

    float acc[4][4][4];
#pragma unroll
    for (int i = 0; i < 4; i++)
#pragma unroll
        for (int j = 0; j < 4; j++)
#pragma unroll
            for (int q = 0; q < 4; q++) acc[i][j][q] = 0.f;

    load_chunk(sbase, 0, Ahi, Alo, Bhi, Blo, rowBase, colBase, 0, tid);
    for (int c = 0; c < 32; ++c) {
        int s = c & 1;
        if (c < 31) {
            load_chunk(sbase, s ^ 1, Ahi, Alo, Bhi, Blo, rowBase, colBase,
                       (c + 1) * 32, tid);
            CP_WAIT1();
        } else {
            CP_WAIT0();
        }
        __syncthreads();
        compute_chunk(acc, sbase + s * STAGE_B, wm, wn, lane);
        __syncthreads();
    }

    // gram epilogue: this tile = side, batches bb..bb+15, 8 query mols each
    const int side = blockIdx.x >> 7;
    const int bb = (blockIdx.x & 127) * 16;
    const float* keys = side ? fP : fR;
    uint32_t zsm = sbase;
    uint32_t fsm = sbase + 64 * FPAD * 4;

#pragma unroll
    for (int pass = 0; pass < 2; pass++) {
        __syncthreads();
        if ((wid >> 2) == pass) {
#pragma unroll
            for (int mt = 0; mt < 4; mt++) {
                int lr = mt * 16 + (lane >> 2);
#pragma unroll
                for (int nt = 0; nt < 4; nt++) {
                    int lc = wn + nt * 8 + (lane & 3) * 2;
                    sts2f(zsm + (lr * FPAD + lc) * 4, acc[mt][nt][0], acc[mt][nt][1]);
                    sts2f(zsm + ((lr + 8) * FPAD + lc) * 4, acc[mt][nt][2], acc[mt][nt][3]);
                }
            }
        }
#pragma unroll
        for (int h = 0; h < 8; h++) {
            int idx = h * 256 + tid;
            int rowi = idx >> 5, ch = idx & 31;
            int bl = rowi >> 3, kk2 = rowi & 7;
            const float* src = keys +
                ((size_t)kk2 * BATCH + (bb + pass * 8 + bl)) * DIM + colBase + ch * 4;
            cpa16(fsm + (rowi * FPAD + ch * 4) * 4, src);
        }
        CP_COMMIT(); CP_WAIT0();
        __syncthreads();

        int bl = wid, kk = lane & 7;
#pragma unroll
        for (int i = 0; i < 2; i++) {
            int q = (lane >> 3) + i * 4;
            uint32_t zr = zsm + ((bl * 8 + q) * FPAD) * 4;
            uint32_t fr = fsm + ((bl * 8 + kk) * FPAD) * 4;
            float s = 0.f;
#pragma unroll
            for (int cc = 0; cc < 128; cc += 4) {
                float4 zv = lds4f(zr + cc * 4);
                float4 fv = lds4f(fr + cc * 4);
                s += zv.x * fv.x + zv.y * fv.y + zv.z * fv.z + zv.w * fv.w;
            }
            g_Spart[((size_t)(blockIdx.y * 2 + side) * BATCH + bb + pass * 8 + bl) * 64
                    + lane + 32 * i] = s;
        }
    }
}

// -------------------- softmax / attention outputs --------------------------
__global__ void __launch_bounds__(128) softmax_kernel(float* __restrict__ d_out) {
    const int b = blockIdx.x;
    const int t = threadIdx.x;
    __shared__ float sS[2][MOL][MOL];
    __shared__ float sProb[2][LQ][LQ];
    __shared__ float sAtt[2][LQ];

    {
        int side = t >> 6, e = t & 63;
        float s = 0.f;
#pragma unroll
        for (int ct = 0; ct < 8; ct++)
            s += g_Spart[((size_t)(ct * 2 + side) * BATCH + b) * 64 + e];
        sS[side][e >> 3][e & 7] = s;
    }
    __syncthreads();

    if (t < 2 * LQ) {
        int sd = t / LQ, qq = t % LQ;
        int qi, qj;
        if (qq < MOL) { qi = qq; qj = -1; }
        else          { qi = c_pi[qq - MOL]; qj = c_pj[qq - MOL]; }
        float row[LQ];
        float maxv = -1e30f;
#pragma unroll
        for (int kk = 0; kk < LQ; kk++) {
            int ki, kj;
            if (kk < MOL) { ki = kk; kj = -1; }
            else          { ki = c_pi[kk - MOL]; kj = c_pj[kk - MOL]; }
            float v = sS[sd][qi][ki];
            if (kj >= 0) v += sS[sd][qi][kj];
            if (qj >= 0) {
                v += sS[sd][qj][ki];
                if (kj >= 0) v += sS[sd][qj][kj];
            }
            v *= 0.03125f;
            row[kk] = v;
            maxv = fmaxf(maxv, v);
        }
        float sum = 0.f;
#pragma unroll
        for (int kk = 0; kk < LQ; kk++) { row[kk] = expf(row[kk] - maxv); sum += row[kk]; }
        float inv = 1.f / sum;
#pragma unroll
        for (int kk = 0; kk < LQ; kk++) sProb[sd][qq][kk] = row[kk] * inv;
    }
    __syncthreads();

    if (t < 2 * LQ) {
        int sd = t / LQ, kk = t % LQ;
        float a = 0.f;
#pragma unroll
        for (int qq = 0; qq < LQ; qq++) a += sProb[sd][qq][kk];
        a *= (1.0f / LQ);
        sAtt[sd][kk] = a;
        d_out[BATCH * OUTD + sd * (BATCH * LQ) + b * LQ + kk] = a;
    }
    __syncthreads();

    if (t < 16) {
        int sd = t >> 3, m = t & 7;
        float w = sAtt[sd][m];
#pragma unroll
        for (int pp = 0; pp < NPAIR; pp++)
            if (c_pi[pp] == m || c_pj[pp] == m) w += sAtt[sd][MOL + pp];
        g_w[sd * BATCH * MOL + b * MOL + m] = w;
    }
}

// ------------------------- pooling + head (float4) -------------------------
__global__ void __launch_bounds__(256) pool_kernel(
    const float* __restrict__ r_feats, const float* __restrict__ p_feats,
    const float* __restrict__ r_new,   const float* __restrict__ p_new,
    const float* __restrict__ W_pred,  const float* __restrict__ b_pred,
    float* __restrict__ d_out)
{
    const int b = blockIdx.x;
    const int t = threadIdx.x;
    __shared__ float sw[16];
    __shared__ float sRed[OUTD][8];
    if (t < 16) sw[t] = g_w[(t >> 3) * BATCH * MOL + b * MOL + (t & 7)];
    __syncthreads();

    const int d = t * 4;
    float4 acc = make_float4(0.f, 0.f, 0.f, 0.f);
#pragma unroll
    for (int m = 0; m < MOL; m++) {
        size_t off = ((size_t)m * BATCH + b) * DIM + d;
        float4 a  = *(const float4*)(r_feats + off);
        float4 an = *(const float4*)(r_new + off);
        float4 pv = *(const float4*)(p_feats + off);
        float4 pn = *(const float4*)(p_new + off);
        float wr = sw[m], wp = sw[8 + m];
        acc.x += wr * (a.x + an.x) - wp * (pv.x + pn.x);
        acc.y += wr * (a.y + an.y) - wp * (pv.y + pn.y);
        acc.z += wr * (a.z + an.z) - wp * (pv.z + pn.z);
        acc.w += wr * (a.w + an.w) - wp * (pv.w + pn.w);
    }
    float part[OUTD];
#pragma unroll
    for (int o = 0; o < OUTD; o++) {
        float4 wv = *(const float4*)(W_pred + (size_t)o * DIM + d);
        part[o] = acc.x * wv.x + acc.y * wv.y + acc.z * wv.z + acc.w * wv.w;
    }
    int lane = t & 31, wid = t >> 5;
#pragma unroll
    for (int o = 0; o < OUTD; o++) {
        float v = part[o];
#pragma unroll
        for (int off = 16; off > 0; off >>= 1)
            v += __shfl_down_sync(0xFFFFFFFFu, v, off);
        if (lane == 0) sRed[o][wid] = v;
    }
    __syncthreads();
    if (t < OUTD) {
        float s = 0.f;
#pragma unroll
        for (int w = 0; w < 8; w++) s += sRed[t][w];
        d_out[b * OUTD + t] = s + b_pred[t];
    }
}

// ---------------------------------------------------------------------------
extern "C" void kernel_launch(void* const* d_in, const int* in_sizes, int n_in,
                              void* d_out, int out_size) {
    const float* r_feats = (const float*)d_in[0];
    const float* p_feats = (const float*)d_in[1];
    const float* r_new   = (const float*)d_in[2];
    const float* p_new   = (const float*)d_in[3];
    const float* Wq      = (const float*)d_in[4];
    const float* Wk      = (const float*)d_in[5];
    const float* W_pred  = (const float*)d_in[6];
    const float* b_pred  = (const float*)d_in[7];
    float* out = (float*)d_out;

    cudaFuncSetAttribute(mma_gemm_plain, cudaFuncAttributeMaxDynamicSharedMemorySize,
                         SMEM_GEMM);
    cudaFuncSetAttribute(mma_gemm_fused, cudaFuncAttributeMaxDynamicSharedMemorySize,
                         SMEM_GEMM);

    __nv_bfloat16 *WqHi, *WqLo, *WkHi, *WkLo, *GtHi, *GtLo, *Xhi, *Xlo;
    float *G;
    cudaGetSymbolAddress((void**)&WqHi, g_WqHi);
    cudaGetSymbolAddress((void**)&WqLo, g_WqLo);
    cudaGetSymbolAddress((void**)&WkHi, g_WkHi);
    cudaGetSymbolAddress((void**)&WkLo, g_WkLo);
    cudaGetSymbolAddress((void**)&GtHi, g_GtHi);
    cudaGetSymbolAddress((void**)&GtLo, g_GtLo);
    cudaGetSymbolAddress((void**)&Xhi,  g_Xhi);
    cudaGetSymbolAddress((void**)&Xlo,  g_Xlo);
    cudaGetSymbolAddress((void**)&G,    g_G);

    split_w<<<2048, 128>>>(Wq, Wk);
    mma_gemm_plain<<<dim3(8, 8), 256, SMEM_GEMM>>>(WqHi, WqLo, WkHi, WkLo, G);
    tsplit_g<<<dim3(32, 32), dim3(32, 8)>>>();
    split_x<<<MROWS / 2, 256>>>(p_feats, r_feats);
    mma_gemm_fused<<<dim3(256, 8), 256, SMEM_GEMM>>>(Xhi, Xlo, GtHi, GtLo,
                                                     r_feats, p_feats);
    softmax_kernel<<<BATCH, 128>>>(out);
    pool_kernel<<<BATCH, 256>>>(r_feats, p_feats, r_new, p_new, W_pred, b_pred, out);
}

// round 7
// speedup vs baseline: 1.2012x; 1.0150x over previous
#include <cuda_runtime.h>
#include <cuda_bf16.h>
#include <cstdint>

constexpr int BATCH = 2048;
constexpr int DIM   = 1024;
constexpr int MOL   = 8;
constexpr int NPAIR = 28;
constexpr int LQ    = 36;
constexpr int OUTD  = 4;
constexpr int MROWS = 32768;           // 2 * BATCH * MOL

__constant__ int c_pi[NPAIR] = {0,0,0,0,0,0,0,1,1,1,1,1,1,2,2,2,2,2,3,3,3,3,4,4,4,5,5,6};
__constant__ int c_pj[NPAIR] = {1,2,3,4,5,6,7,2,3,4,5,6,7,3,4,5,6,7,4,5,6,7,5,6,7,6,7,7};

// ------------------------- static device scratch ---------------------------
__device__ __nv_bfloat16 g_WqHi[DIM * DIM];
__device__ __nv_bfloat16 g_WqLo[DIM * DIM];
__device__ __nv_bfloat16 g_WkHi[DIM * DIM];
__device__ __nv_bfloat16 g_WkLo[DIM * DIM];
__device__ __nv_bfloat16 g_GtHi[DIM * DIM];          // Gt[n][k] = G[k][n]
__device__ __nv_bfloat16 g_GtLo[DIM * DIM];
__device__ __nv_bfloat16 g_Xhi[(size_t)MROWS * DIM]; // 64 MB, row = s*16384+b*8+m
__device__ __nv_bfloat16 g_Xlo[(size_t)MROWS * DIM]; // 64 MB
__device__ float         g_Spart[8ull * 2 * BATCH * 64];  // 4 MB partial grams
__device__ float         g_w[2 * BATCH * MOL];

// ------------------------------ helpers ------------------------------------
__device__ __forceinline__ uint32_t s2u(const void* p) {
    uint32_t a;
    asm("{ .reg .u64 t; cvta.to.shared.u64 t, %1; cvt.u32.u64 %0, t; }" : "=r"(a) : "l"(p));
    return a;
}
__device__ __forceinline__ void cpa16(uint32_t d, const void* g) {
    asm volatile("cp.async.cg.shared.global [%0], [%1], 16;" :: "r"(d), "l"(g));
}
#define CP_COMMIT()  asm volatile("cp.async.commit_group;" ::: "memory")
#define CP_WAIT0()   asm volatile("cp.async.wait_group 0;" ::: "memory")

__device__ __forceinline__ float4 lds4f(uint32_t a) {
    float4 v;
    asm volatile("ld.shared.v4.f32 {%0,%1,%2,%3}, [%4];"
        : "=f"(v.x), "=f"(v.y), "=f"(v.z), "=f"(v.w) : "r"(a));
    return v;
}
__device__ __forceinline__ float lds1f(uint32_t a) {
    float v;
    asm volatile("ld.shared.f32 %0, [%1];" : "=f"(v) : "r"(a));
    return v;
}
__device__ __forceinline__ void sts2f(uint32_t a, float x, float y) {
    asm volatile("st.shared.v2.f32 [%0], {%1,%2};" :: "r"(a), "f"(x), "f"(y));
}

__device__ __forceinline__ void lda4(uint32_t* f, uint32_t mbase, int wm, int mt,
                                     int ks, int lane) {
    int g = lane >> 3, r = lane & 7;
    int mloc = wm + mt * 16 + (g & 1) * 8 + r;
    int kloc = ks * 16 + (g >> 1) * 8;
    uint32_t a = mbase + (mloc * 40 + kloc) * 2;
    asm volatile("ldmatrix.sync.aligned.m8n8.x4.shared.b16 {%0,%1,%2,%3}, [%4];"
        : "=r"(f[0]), "=r"(f[1]), "=r"(f[2]), "=r"(f[3]) : "r"(a));
}
__device__ __forceinline__ void ldb2(uint32_t* f, uint32_t mbase, int wn, int nt,
                                     int ks, int lane) {
    int l = lane & 15;
    int g = l >> 3, r = l & 7;
    int nloc = wn + nt * 8 + r;
    int kloc = ks * 16 + g * 8;
    uint32_t a = mbase + (nloc * 40 + kloc) * 2;
    asm volatile("ldmatrix.sync.aligned.m8n8.x2.shared.b16 {%0,%1}, [%2];"
        : "=r"(f[0]), "=r"(f[1]) : "r"(a));
}
__device__ __forceinline__ void mma16816(float* c, const uint32_t* a, const uint32_t* b) {
    asm volatile("mma.sync.aligned.m16n8k16.row.col.f32.bf16.bf16.f32 "
        "{%0,%1,%2,%3}, {%4,%5,%6,%7}, {%8,%9}, {%0,%1,%2,%3};"
        : "+f"(c[0]), "+f"(c[1]), "+f"(c[2]), "+f"(c[3])
        : "r"(a[0]), "r"(a[1]), "r"(a[2]), "r"(a[3]), "r"(b[0]), "r"(b[1]));
}

union BfPack { __nv_bfloat16 h[8]; uint4 u; };

// ------------------------- split kernels -----------------------------------
__global__ void __launch_bounds__(128) split_w(const float* __restrict__ Wq,
                                               const float* __restrict__ Wk) {
    int bx = blockIdx.x;
    int mat = bx >> 10, row = bx & 1023;
    const float* src = (mat ? Wk : Wq) + (size_t)row * DIM;
    __nv_bfloat16* hi = (mat ? g_WkHi : g_WqHi) + (size_t)row * DIM;
    __nv_bfloat16* lo = (mat ? g_WkLo : g_WqLo) + (size_t)row * DIM;
    int t = threadIdx.x;
    float4 v0 = ((const float4*)src)[t * 2];
    float4 v1 = ((const float4*)src)[t * 2 + 1];
    float vv[8] = {v0.x, v0.y, v0.z, v0.w, v1.x, v1.y, v1.z, v1.w};
    BfPack hp, lp;
#pragma unroll
    for (int i = 0; i < 8; i++) {
        __nv_bfloat16 h = __float2bfloat16_rn(vv[i]);
        hp.h[i] = h;
        lp.h[i] = __float2bfloat16_rn(vv[i] - __bfloat162float(h));
    }
    ((uint4*)(hi))[t] = hp.u;
    ((uint4*)(lo))[t] = lp.u;
}

__global__ void __launch_bounds__(256) split_x(const float* __restrict__ p,
                                               const float* __restrict__ r) {
    int t = threadIdx.x;
    int row = blockIdx.x * 2 + (t >> 7);
    int tt = t & 127;
    int s = row >> 14, b = (row >> 3) & (BATCH - 1), m = row & 7;
    const float* src = (s ? r : p) + ((size_t)m * BATCH + b) * DIM;
    float4 v0 = ((const float4*)src)[tt * 2];
    float4 v1 = ((const float4*)src)[tt * 2 + 1];
    float vv[8] = {v0.x, v0.y, v0.z, v0.w, v1.x, v1.y, v1.z, v1.w};
    BfPack hp, lp;
#pragma unroll
    for (int i = 0; i < 8; i++) {
        __nv_bfloat16 h = __float2bfloat16_rn(vv[i]);
        hp.h[i] = h;
        lp.h[i] = __float2bfloat16_rn(vv[i] - __bfloat162float(h));
    }
    ((uint4*)(g_Xhi + (size_t)row * DIM))[tt] = hp.u;
    ((uint4*)(g_Xlo + (size_t)row * DIM))[tt] = lp.u;
}

// ------------------------- shared GEMM machinery ---------------------------
constexpr int MAT_ELE   = 128 * 40;
constexpr int STAGE_B   = 4 * MAT_ELE * 2;      // 40960 bytes
constexpr int SMEM_GEMM = 2 * STAGE_B;          // 81920 bytes
constexpr int FPAD      = 132;

__device__ __forceinline__ void load_chunk(
    uint32_t sbase, int stage,
    const __nv_bfloat16* __restrict__ Ahi, const __nv_bfloat16* __restrict__ Alo,
    const __nv_bfloat16* __restrict__ Bhi, const __nv_bfloat16* __restrict__ Blo,
    int rowBase, int colBase, int k0, int tid)
{
    uint32_t st = sbase + stage * STAGE_B;
#pragma unroll
    for (int mat = 0; mat < 4; mat++) {
        const __nv_bfloat16* src0 =
            (mat == 0) ? Ahi : (mat == 1) ? Alo : (mat == 2) ? Bhi : Blo;
        int base = (mat < 2) ? rowBase : colBase;
#pragma unroll
        for (int h = 0; h < 2; h++) {
            int idx = h * 256 + tid;
            int row = idx >> 2, ch = idx & 3;
            const __nv_bfloat16* src = src0 + (size_t)(base + row) * DIM + k0 + ch * 8;
            uint32_t dst = st + (mat * MAT_ELE + row * 40 + ch * 8) * 2;
            cpa16(dst, src);
        }
    }
    CP_COMMIT();
}

// inner compute for one k32 chunk; B frags held, A streamed per mt
__device__ __forceinline__ void compute_chunk(
    float acc[4][4][4], uint32_t stb, int wm, int wn, int lane)
{
    uint32_t bAhi = stb;
    uint32_t bAlo = stb + MAT_ELE * 2;
    uint32_t bBhi = stb + 2 * MAT_ELE * 2;
    uint32_t bBlo = stb + 3 * MAT_ELE * 2;
#pragma unroll
    for (int ks = 0; ks < 2; ks++) {
        uint32_t bhif[4][2], blof[4][2];
#pragma unroll
        for (int nt = 0; nt < 4; nt++) {
            ldb2(bhif[nt], bBhi, wn, nt, ks, lane);
            ldb2(blof[nt], bBlo, wn, nt, ks, lane);
        }
#pragma unroll
        for (int mt = 0; mt < 4; mt++) {
            uint32_t ahif[4], alof[4];
            lda4(ahif, bAhi, wm, mt, ks, lane);
            lda4(alof, bAlo, wm, mt, ks, lane);
#pragma unroll
            for (int nt = 0; nt < 4; nt++) {
                mma16816(acc[mt][nt], ahif, bhif[nt]);
                mma16816(acc[mt][nt], alof, bhif[nt]);
                mma16816(acc[mt][nt], ahif, blof[nt]);
            }
        }
    }
}

// single-sync mainloop: wait -> sync -> prefetch(c+1) -> compute(c)
#define GEMM_MAINLOOP()                                                        \
    load_chunk(sbase, 0, Ahi, Alo, Bhi, Blo, rowBase, colBase, 0, tid);        \
    for (int c = 0; c < 32; ++c) {                                             \
        int s = c & 1;                                                         \
        CP_WAIT0();                                                            \
        __syncthreads();                                                       \
        if (c < 31)                                                            \
            load_chunk(sbase, s ^ 1, Ahi, Alo, Bhi, Blo, rowBase, colBase,     \
                       (c + 1) * 32, tid);                                     \
        compute_chunk(acc, sbase + s * STAGE_B, wm, wn, lane);                 \
    }

// --------- G GEMM: C = Wq@Wk^T, epilogue writes Gt hi/lo (transposed) ------
__global__ void __launch_bounds__(256) mma_gemm_g(
    const __nv_bfloat16* __restrict__ Ahi, const __nv_bfloat16* __restrict__ Alo,
    const __nv_bfloat16* __restrict__ Bhi, const __nv_bfloat16* __restrict__ Blo)
{
    extern __shared__ char smem[];
    uint32_t sbase = s2u(smem);
    const int tid  = threadIdx.x;
    const int lane = tid & 31;
    const int wid  = tid >> 5;
    const int wm = (wid >> 2) * 64;
    const int wn = (wid & 3) * 32;
    const int rowBase = blockIdx.x * 128;   // k of Gt
    const int colBase = blockIdx.y * 128;   // n of Gt

    float acc[4][4][4];
#pragma unroll
    for (int i = 0; i < 4; i++)
#pragma unroll
        for (int j = 0; j < 4; j++)
#pragma unroll
            for (int q = 0; q < 4; q++) acc[i][j][q] = 0.f;

    GEMM_MAINLOOP();

    // stage fp32 tile in smem: [k_local 0..127][n_local 0..127], stride FPAD
    __syncthreads();
#pragma unroll
    for (int mt = 0; mt < 4; mt++) {
        int lr = wm + mt * 16 + (lane >> 2);
#pragma unroll
        for (int nt = 0; nt < 4; nt++) {
            int lc = wn + nt * 8 + (lane & 3) * 2;
            sts2f(sbase + (lr * FPAD + lc) * 4, acc[mt][nt][0], acc[mt][nt][1]);
            sts2f(sbase + ((lr + 8) * FPAD + lc) * 4, acc[mt][nt][2], acc[mt][nt][3]);
        }
    }
    __syncthreads();

    // transpose-read + split + coalesced bf16 store
    int n_local = tid >> 1;
    int kh = (tid & 1) * 64;
    size_t gbase = (size_t)(colBase + n_local) * DIM + rowBase + kh;
#pragma unroll
    for (int kb = 0; kb < 64; kb += 8) {
        BfPack hp, lp;
#pragma unroll
        for (int i = 0; i < 8; i++) {
            float v = lds1f(sbase + ((kh + kb + i) * FPAD + n_local) * 4);
            __nv_bfloat16 h = __float2bfloat16_rn(v);
            hp.h[i] = h;
            lp.h[i] = __float2bfloat16_rn(v - __bfloat162float(h));
        }
        *(uint4*)(g_GtHi + gbase + kb) = hp.u;
        *(uint4*)(g_GtLo + gbase + kb) = lp.u;
    }
}

// --------------- fused GEMM (Z = X@G) + gram epilogue ----------------------
__global__ void __launch_bounds__(256, 2) mma_gemm_fused(
    const __nv_bfloat16* __restrict__ Ahi, const __nv_bfloat16* __restrict__ Alo,
    const __nv_bfloat16* __restrict__ Bhi, const __nv_bfloat16* __restrict__ Blo,
    const float* __restrict__ fR, const float* __restrict__ fP)
{
    extern __shared__ char smem[];
    uint32_t sbase = s2u(smem);
    const int tid  = threadIdx.x;
    const int lane = tid & 31;
    const int wid  = tid >> 5;
    const int wm = (wid >> 2) * 64;
    const int wn = (wid & 3) * 32;
    const int rowBase = blockIdx.x * 128;
    const int colBase = blockIdx.y * 128;

    float acc[4][4][4];
#pragma unroll
    for (int i = 0; i < 4; i++)
#pragma unroll
        for (int j = 0; j < 4; j++)
#pragma unroll
            for (int q = 0; q < 4; q++) acc[i][j][q] = 0.f;

    GEMM_MAINLOOP();

    // gram epilogue: tile = side, batches bb..bb+15, 8 query mols
    const int side = blockIdx.x >> 7;
    const int bb = (blockIdx.x & 127) * 16;
    const float* keys = side ? fP : fR;
    uint32_t zsm = sbase;
    uint32_t fsm = sbase + 64 * FPAD * 4;

#pragma unroll
    for (int pass = 0; pass < 2; pass++) {
        __syncthreads();
        if ((wid >> 2) == pass) {
#pragma unroll
            for (int mt = 0; mt < 4; mt++) {
                int lr = mt * 16 + (lane >> 2);
#pragma unroll
                for (int nt = 0; nt < 4; nt++) {
                    int lc = wn + nt * 8 + (lane & 3) * 2;
                    sts2f(zsm + (lr * FPAD + lc) * 4, acc[mt][nt][0], acc[mt][nt][1]);
                    sts2f(zsm + ((lr + 8) * FPAD + lc) * 4, acc[mt][nt][2], acc[mt][nt][3]);
                }
            }
        }
#pragma unroll
        for (int h = 0; h < 8; h++) {
            int idx = h * 256 + tid;
            int rowi = idx >> 5, ch = idx & 31;
            int bl = rowi >> 3, kk2 = rowi & 7;
            const float* src = keys +
                ((size_t)kk2 * BATCH + (bb + pass * 8 + bl)) * DIM + colBase + ch * 4;
            cpa16(fsm + (rowi * FPAD + ch * 4) * 4, src);
        }
        CP_COMMIT(); CP_WAIT0();
        __syncthreads();

        int bl = wid, kk = lane & 7;
#pragma unroll
        for (int i = 0; i < 2; i++) {
            int q = (lane >> 3) + i * 4;
            uint32_t zr = zsm + ((bl * 8 + q) * FPAD) * 4;
            uint32_t fr = fsm + ((bl * 8 + kk) * FPAD) * 4;
            float s = 0.f;
#pragma unroll
            for (int cc = 0; cc < 128; cc += 4) {
                float4 zv = lds4f(zr + cc * 4);
                float4 fv = lds4f(fr + cc * 4);
                s += zv.x * fv.x + zv.y * fv.y + zv.z * fv.z + zv.w * fv.w;
            }
            g_Spart[((size_t)(blockIdx.y * 2 + side) * BATCH + bb + pass * 8 + bl) * 64
                    + lane + 32 * i] = s;
        }
    }
}

// -------------------- softmax / attention outputs --------------------------
__global__ void __launch_bounds__(128) softmax_kernel(float* __restrict__ d_out) {
    const int b = blockIdx.x;
    const int t = threadIdx.x;
    __shared__ float sS[2][MOL][MOL];
    __shared__ float sProb[2][LQ][LQ];
    __shared__ float sAtt[2][LQ];

    {
        int side = t >> 6, e = t & 63;
        float s = 0.f;
#pragma unroll
        for (int ct = 0; ct < 8; ct++)
            s += g_Spart[((size_t)(ct * 2 + side) * BATCH + b) * 64 + e];
        sS[side][e >> 3][e & 7] = s;
    }
    __syncthreads();

    if (t < 2 * LQ) {
        int sd = t / LQ, qq = t % LQ;
        int qi, qj;
        if (qq < MOL) { qi = qq; qj = -1; }
        else          { qi = c_pi[qq - MOL]; qj = c_pj[qq - MOL]; }
        float row[LQ];
        float maxv = -1e30f;
#pragma unroll
        for (int kk = 0; kk < LQ; kk++) {
            int ki, kj;
            if (kk < MOL) { ki = kk; kj = -1; }
            else          { ki = c_pi[kk - MOL]; kj = c_pj[kk - MOL]; }
            float v = sS[sd][qi][ki];
            if (kj >= 0) v += sS[sd][qi][kj];
            if (qj >= 0) {
                v += sS[sd][qj][ki];
                if (kj >= 0) v += sS[sd][qj][kj];
            }
            v *= 0.03125f;
            row[kk] = v;
            maxv = fmaxf(maxv, v);
        }
        float sum = 0.f;
#pragma unroll
        for (int kk = 0; kk < LQ; kk++) { row[kk] = expf(row[kk] - maxv); sum += row[kk]; }
        float inv = 1.f / sum;
#pragma unroll
        for (int kk = 0; kk < LQ; kk++) sProb[sd][qq][kk] = row[kk] * inv;
    }
    __syncthreads();

    if (t < 2 * LQ) {
        int sd = t / LQ, kk = t % LQ;
        float a = 0.f;
#pragma unroll
        for (int qq = 0; qq < LQ; qq++) a += sProb[sd][qq][kk];
        a *= (1.0f / LQ);
        sAtt[sd][kk] = a;
        d_out[BATCH * OUTD + sd * (BATCH * LQ) + b * LQ + kk] = a;
    }
    __syncthreads();

    if (t < 16) {
        int sd = t >> 3, m = t & 7;
        float w = sAtt[sd][m];
#pragma unroll
        for (int pp = 0; pp < NPAIR; pp++)
            if (c_pi[pp] == m || c_pj[pp] == m) w += sAtt[sd][MOL + pp];
        g_w[sd * BATCH * MOL + b * MOL + m] = w;
    }
}

// ------------------------- pooling + head (float4) -------------------------
__global__ void __launch_bounds__(256) pool_kernel(
    const float* __restrict__ r_feats, const float* __restrict__ p_feats,
    const float* __restrict__ r_new,   const float* __restrict__ p_new,
    const float* __restrict__ W_pred,  const float* __restrict__ b_pred,
    float* __restrict__ d_out)
{
    const int b = blockIdx.x;
    const int t = threadIdx.x;
    __shared__ float sw[16];
    __shared__ float sRed[OUTD][8];
    if (t < 16) sw[t] = g_w[(t >> 3) * BATCH * MOL + b * MOL + (t & 7)];
    __syncthreads();

    const int d = t * 4;
    float4 acc = make_float4(0.f, 0.f, 0.f, 0.f);
#pragma unroll
    for (int m = 0; m < MOL; m++) {
        size_t off = ((size_t)m * BATCH + b) * DIM + d;
        float4 a  = *(const float4*)(r_feats + off);
        float4 an = *(const float4*)(r_new + off);
        float4 pv = *(const float4*)(p_feats + off);
        float4 pn = *(const float4*)(p_new + off);
        float wr = sw[m], wp = sw[8 + m];
        acc.x += wr * (a.x + an.x) - wp * (pv.x + pn.x);
        acc.y += wr * (a.y + an.y) - wp * (pv.y + pn.y);
        acc.z += wr * (a.z + an.z) - wp * (pv.z + pn.z);
        acc.w += wr * (a.w + an.w) - wp * (pv.w + pn.w);
    }
    float part[OUTD];
#pragma unroll
    for (int o = 0; o < OUTD; o++) {
        float4 wv = *(const float4*)(W_pred + (size_t)o * DIM + d);
        part[o] = acc.x * wv.x + acc.y * wv.y + acc.z * wv.z + acc.w * wv.w;
    }
    int lane = t & 31, wid = t >> 5;
#pragma unroll
    for (int o = 0; o < OUTD; o++) {
        float v = part[o];
#pragma unroll
        for (int off = 16; off > 0; off >>= 1)
            v += __shfl_down_sync(0xFFFFFFFFu, v, off);
        if (lane == 0) sRed[o][wid] = v;
    }
    __syncthreads();
    if (t < OUTD) {
        float s = 0.f;
#pragma unroll
        for (int w = 0; w < 8; w++) s += sRed[t][w];
        d_out[b * OUTD + t] = s + b_pred[t];
    }
}

// ---------------------------------------------------------------------------
extern "C" void kernel_launch(void* const* d_in, const int* in_sizes, int n_in,
                              void* d_out, int out_size) {
    const float* r_feats = (const float*)d_in[0];
    const float* p_feats = (const float*)d_in[1];
    const float* r_new   = (const float*)d_in[2];
    const float* p_new   = (const float*)d_in[3];
    const float* Wq      = (const float*)d_in[4];
    const float* Wk      = (const float*)d_in[5];
    const float* W_pred  = (const float*)d_in[6];
    const float* b_pred  = (const float*)d_in[7];
    float* out = (float*)d_out;

    cudaFuncSetAttribute(mma_gemm_g, cudaFuncAttributeMaxDynamicSharedMemorySize,
                         SMEM_GEMM);
    cudaFuncSetAttribute(mma_gemm_fused, cudaFuncAttributeMaxDynamicSharedMemorySize,
                         SMEM_GEMM);

    __nv_bfloat16 *WqHi, *WqLo, *WkHi, *WkLo, *GtHi, *GtLo, *Xhi, *Xlo;
    cudaGetSymbolAddress((void**)&WqHi, g_WqHi);
    cudaGetSymbolAddress((void**)&WqLo, g_WqLo);
    cudaGetSymbolAddress((void**)&WkHi, g_WkHi);
    cudaGetSymbolAddress((void**)&WkLo, g_WkLo);
    cudaGetSymbolAddress((void**)&GtHi, g_GtHi);
    cudaGetSymbolAddress((void**)&GtLo, g_GtLo);
    cudaGetSymbolAddress((void**)&Xhi,  g_Xhi);
    cudaGetSymbolAddress((void**)&Xlo,  g_Xlo);

    // 1) weight splits
    split_w<<<2048, 128>>>(Wq, Wk);
    // 2) G = Wq @ Wk^T, epilogue writes Gt hi/lo directly (no fp32 G)
    mma_gemm_g<<<dim3(8, 8), 256, SMEM_GEMM>>>(WqHi, WqLo, WkHi, WkLo);
    // 3) gather+split X
    split_x<<<MROWS / 2, 256>>>(p_feats, r_feats);
    // 4) fused GEMM + gram epilogue (slot 4 for ncu)
    mma_gemm_fused<<<dim3(256, 8), 256, SMEM_GEMM>>>(Xhi, Xlo, GtHi, GtLo,
                                                     r_feats, p_feats);
    // 5) softmax / attention outputs
    softmax_kernel<<<BATCH, 128>>>(out);
    // 6) pooling + head
    pool_kernel<<<BATCH, 256>>>(r_feats, p_feats, r_new, p_new, W_pred, b_pred, out);
}